// round 1
// baseline (speedup 1.0000x reference)
#include <cuda_runtime.h>
#include <math.h>

// Problem constants
#define RR   1024        // num rois
#define GG   16          // groups
#define DD   1024        // feature dim
#define DGB  64          // per-group dim
#define EE   64          // pos-emb dim
#define KFC1 12544       // 256*7*7

// ---------------- scratch (static device globals; no allocation) ----------------
__device__ float g_h  [RR*DD];
__device__ float g_h2 [RR*DD];
__device__ float g_q  [RR*DD];
__device__ float g_k  [RR*DD];
__device__ float g_v  [RR*DD];
__device__ float g_att[RR*DD];
__device__ float g_S  [(long)GG*RR*RR];   // [g][i][j]
__device__ float g_B1 [(long)RR*GG*RR];   // log-bias block1: [r][g][n]
__device__ float g_B2 [(long)RR*GG*RR];   // log-bias block2

// ---------------- position bias kernel ----------------
// out{1,2}[r][g][n] = log(max( pe[r,n,:]·Wp{1,2}[g,:] + bp{1,2}[g], 1e-6 ))
__global__ __launch_bounds__(128)
void posbias_kernel(const float* __restrict__ pe,
                    const float* __restrict__ Wp1, const float* __restrict__ bp1,
                    const float* __restrict__ Wp2, const float* __restrict__ bp2,
                    float* __restrict__ out1, float* __restrict__ out2)
{
    const int r = blockIdx.x;
    const int n = blockIdx.y * 128 + threadIdx.x;

    __shared__ float w1[GG][EE], w2[GG][EE];
    __shared__ float b1s[GG], b2s[GG];
    for (int idx = threadIdx.x; idx < GG*EE; idx += 128) {
        w1[idx >> 6][idx & 63] = Wp1[idx];
        w2[idx >> 6][idx & 63] = Wp2[idx];
    }
    if (threadIdx.x < GG) { b1s[threadIdx.x] = bp1[threadIdx.x]; b2s[threadIdx.x] = bp2[threadIdx.x]; }
    __syncthreads();

    float4 pr[EE/4];
    const float4* src = (const float4*)(pe + (((long)r * RR) + n) * EE);
#pragma unroll
    for (int i = 0; i < EE/4; i++) pr[i] = src[i];

#pragma unroll 1
    for (int g = 0; g < GG; ++g) {
        const float4* a = (const float4*)w1[g];
        const float4* b = (const float4*)w2[g];
        float s1 = 0.f, s2 = 0.f;
#pragma unroll
        for (int i = 0; i < EE/4; i++) {
            float4 p = pr[i], xx = a[i], yy = b[i];
            s1 += p.x*xx.x + p.y*xx.y + p.z*xx.z + p.w*xx.w;
            s2 += p.x*yy.x + p.y*yy.y + p.z*yy.z + p.w*yy.w;
        }
        long o = ((long)r * GG + g) * RR + n;
        out1[o] = logf(fmaxf(s1 + b1s[g], 1e-6f));
        out2[o] = logf(fmaxf(s2 + b2s[g], 1e-6f));
    }
}

// ---------------- generic tiled SGEMM ----------------
// C[M,N] = alpha * A @ op(B) + bias, optional relu.
//   BT=true : B is [N,K] row-major (i.e. C = A @ B^T)  -- weight layout
//   BT=false: B is [K,N] row-major (i.e. C = A @ B)
//   CONCAT  : virtual A = [h | a | h+a] over K=3072 (A=h, A2=a)
// z-batching via aZ/bZ/cZ/biasZ element offsets per blockIdx.z.
template<int BM,int BN,int BK,int TM,int TN,bool BT,bool CONCAT>
__global__ void __launch_bounds__((BM/TM)*(BN/TN))
gemm_k(const float* __restrict__ A, const float* __restrict__ A2, int lda,
       const float* __restrict__ B, int ldb,
       float* __restrict__ C, int ldc,
       int M, int N, int K, float alpha,
       const float* __restrict__ bias, int doRelu,
       long aZ, long bZ, long cZ, long biasZ)
{
    constexpr int THREADS = (BM/TM)*(BN/TN);
    constexpr int LA = (BM*BK)/(4*THREADS);
    constexpr int LB = (BN*BK)/(4*THREADS);
    static_assert(LA >= 1 && LB >= 1, "tile/thread mismatch");

    const int tid = threadIdx.x;
    const int tx  = tid % (BN/TN);
    const int ty  = tid / (BN/TN);
    const int m0  = blockIdx.y * BM;
    const int n0  = blockIdx.x * BN;
    const long z  = blockIdx.z;

    A += z * aZ;
    if (CONCAT) A2 += z * aZ;
    B += z * bZ;
    C += z * cZ;
    const float* biasP = bias ? (bias + z * biasZ) : nullptr;

    __shared__ float As[BK][BM];
    __shared__ float Bs[BK][BN];

    float acc[TM][TN];
#pragma unroll
    for (int i = 0; i < TM; i++)
#pragma unroll
        for (int j = 0; j < TN; j++) acc[i][j] = 0.f;

    float4 pa[LA], pb[LB];

    auto loadA4 = [&](int row, int col) -> float4 {
        if (!CONCAT) {
            return *(const float4*)(A + (long)row * lda + col);
        } else {
            if (col < DD) {
                return *(const float4*)(A + (long)row * DD + col);
            } else if (col < 2*DD) {
                return *(const float4*)(A2 + (long)row * DD + (col - DD));
            } else {
                float4 h4 = *(const float4*)(A  + (long)row * DD + (col - 2*DD));
                float4 a4 = *(const float4*)(A2 + (long)row * DD + (col - 2*DD));
                return make_float4(h4.x+a4.x, h4.y+a4.y, h4.z+a4.z, h4.w+a4.w);
            }
        }
    };

    auto gload = [&](int t) {
        const int k0 = t * BK;
#pragma unroll
        for (int i = 0; i < LA; i++) {
            int idx = tid + i * THREADS;
            int am  = idx / (BK/4);
            int ak  = (idx % (BK/4)) * 4;
            pa[i] = loadA4(m0 + am, k0 + ak);
        }
#pragma unroll
        for (int i = 0; i < LB; i++) {
            int idx = tid + i * THREADS;
            if (BT) {
                int bn = idx / (BK/4);
                int bk = (idx % (BK/4)) * 4;
                pb[i] = *(const float4*)(B + (long)(n0 + bn) * ldb + k0 + bk);
            } else {
                int bk = idx / (BN/4);
                int bn = (idx % (BN/4)) * 4;
                pb[i] = *(const float4*)(B + (long)(k0 + bk) * ldb + n0 + bn);
            }
        }
    };

    auto smstore = [&]() {
#pragma unroll
        for (int i = 0; i < LA; i++) {
            int idx = tid + i * THREADS;
            int am  = idx / (BK/4);
            int ak  = (idx % (BK/4)) * 4;
            As[ak+0][am] = pa[i].x; As[ak+1][am] = pa[i].y;
            As[ak+2][am] = pa[i].z; As[ak+3][am] = pa[i].w;
        }
#pragma unroll
        for (int i = 0; i < LB; i++) {
            int idx = tid + i * THREADS;
            if (BT) {
                int bn = idx / (BK/4);
                int bk = (idx % (BK/4)) * 4;
                Bs[bk+0][bn] = pb[i].x; Bs[bk+1][bn] = pb[i].y;
                Bs[bk+2][bn] = pb[i].z; Bs[bk+3][bn] = pb[i].w;
            } else {
                int bk = idx / (BN/4);
                int bn = (idx % (BN/4)) * 4;
                *(float4*)&Bs[bk][bn] = pb[i];
            }
        }
    };

    const int ntiles = K / BK;
    gload(0);
    smstore();
    __syncthreads();

    for (int t = 0; t < ntiles; t++) {
        if (t + 1 < ntiles) gload(t + 1);   // register prefetch of next tile
#pragma unroll
        for (int kk = 0; kk < BK; kk++) {
            float af[TM], bf[TN];
#pragma unroll
            for (int i = 0; i < TM/4; i++)
                *(float4*)&af[i*4] = *(const float4*)&As[kk][ty*TM + i*4];
#pragma unroll
            for (int j = 0; j < TN/4; j++)
                *(float4*)&bf[j*4] = *(const float4*)&Bs[kk][tx*TN + j*4];
#pragma unroll
            for (int i = 0; i < TM; i++)
#pragma unroll
                for (int j = 0; j < TN; j++)
                    acc[i][j] = fmaf(af[i], bf[j], acc[i][j]);
        }
        if (t + 1 < ntiles) {
            __syncthreads();
            smstore();
            __syncthreads();
        }
    }

    float bb[TN];
#pragma unroll
    for (int j = 0; j < TN; j++) bb[j] = biasP ? biasP[n0 + tx*TN + j] : 0.f;
#pragma unroll
    for (int i = 0; i < TM; i++) {
        int m = m0 + ty*TM + i;
        float4 vo;
        float* vv = &vo.x;
#pragma unroll
        for (int j = 0; j < TN; j++) {
            float r = acc[i][j] * alpha + bb[j];
            if (doRelu) r = fmaxf(r, 0.f);
            vv[j] = r;
        }
        *(float4*)(C + (long)m * ldc + n0 + tx*TN) = vo;
    }
}

// ---------------- fused bias-add + softmax over j ----------------
// S[g][i][:] = softmax( S[g][i][:] + biasLog[i][g][:] )
__global__ __launch_bounds__(256)
void softmax_kernel(float* __restrict__ S, const float* __restrict__ bias)
{
    const int i = blockIdx.x;
    const int g = blockIdx.y;
    float* row = S + ((long)g * RR + i) * RR;
    const float* brow = bias + ((long)i * GG + g) * RR;
    const int tid = threadIdx.x;

    float w[4];
    float mx = -1e30f;
#pragma unroll
    for (int j = 0; j < 4; j++) {
        int c = tid + j * 256;
        w[j] = row[c] + brow[c];
        mx = fmaxf(mx, w[j]);
    }
    __shared__ float red[8];
#pragma unroll
    for (int o = 16; o > 0; o >>= 1) mx = fmaxf(mx, __shfl_xor_sync(0xffffffffu, mx, o));
    if ((tid & 31) == 0) red[tid >> 5] = mx;
    __syncthreads();
    float m2 = red[0];
#pragma unroll
    for (int kk = 1; kk < 8; kk++) m2 = fmaxf(m2, red[kk]);

    float sum = 0.f;
#pragma unroll
    for (int j = 0; j < 4; j++) { w[j] = __expf(w[j] - m2); sum += w[j]; }
#pragma unroll
    for (int o = 16; o > 0; o >>= 1) sum += __shfl_xor_sync(0xffffffffu, sum, o);
    __syncthreads();
    if ((tid & 31) == 0) red[tid >> 5] = sum;
    __syncthreads();
    float s2 = 0.f;
#pragma unroll
    for (int kk = 0; kk < 8; kk++) s2 += red[kk];
    float inv = 1.f / s2;
#pragma unroll
    for (int j = 0; j < 4; j++) row[tid + j * 256] = w[j] * inv;
}

// ---------------- host-side orchestration ----------------
static void relation_block(const float* h, float* q, float* k, float* v,
                           float* S, float* att,
                           const float* Wq, const float* bq,
                           const float* Wk, const float* bk,
                           const float* Wo, const float* bo,
                           const float* biasLog)
{
    // Q = h Wq^T + bq ; K = h Wk^T + bk ; V = h Wo^T   (grouped output proj folded in)
    gemm_k<64,64,16,4,4,true,false><<<dim3(16,16,1),256>>>(
        h,nullptr,DD, Wq,DD, q,DD, RR,DD,DD, 1.f, bq,0, 0,0,0,0);
    gemm_k<64,64,16,4,4,true,false><<<dim3(16,16,1),256>>>(
        h,nullptr,DD, Wk,DD, k,DD, RR,DD,DD, 1.f, bk,0, 0,0,0,0);
    gemm_k<64,64,16,4,4,true,false><<<dim3(16,16,1),256>>>(
        h,nullptr,DD, Wo,DD, v,DD, RR,DD,DD, 1.f, nullptr,0, 0,0,0,0);
    // S[g] = 0.125 * Q_g K_g^T   (batched over 16 groups via grid.z)
    gemm_k<128,64,16,8,4,true,false><<<dim3(16,8,GG),256>>>(
        q,nullptr,DD, k,DD, S,RR, RR,RR,DGB, 0.125f, nullptr,0,
        DGB, DGB, (long)RR*RR, 0);
    // softmax with log-bias
    softmax_kernel<<<dim3(RR,GG),256>>>(S, biasLog);
    // att[:, g*64:(g+1)*64] = A_g @ V_g + bo_g
    gemm_k<64,64,16,4,4,false,false><<<dim3(1,16,GG),256>>>(
        S,nullptr,RR, v,DD, att,DD, RR,DGB,RR, 1.f, bo,0,
        (long)RR*RR, DGB, DGB, DGB);
}

extern "C" void kernel_launch(void* const* d_in, const int* in_sizes, int n_in,
                              void* d_out, int out_size)
{
    const float* x    = (const float*)d_in[0];
    const float* pe   = (const float*)d_in[1];
    const float* Wfc1 = (const float*)d_in[2];
    const float* bfc1 = (const float*)d_in[3];
    const float* Wfc2 = (const float*)d_in[4];
    const float* bfc2 = (const float*)d_in[5];
    const float* Wp1  = (const float*)d_in[6];
    const float* bp1  = (const float*)d_in[7];
    const float* Wq1  = (const float*)d_in[8];
    const float* bq1  = (const float*)d_in[9];
    const float* Wk1  = (const float*)d_in[10];
    const float* bk1  = (const float*)d_in[11];
    const float* Wo1  = (const float*)d_in[12];
    const float* bo1  = (const float*)d_in[13];
    const float* Wa1  = (const float*)d_in[14];
    const float* ba1  = (const float*)d_in[15];
    const float* Wp2  = (const float*)d_in[16];
    const float* bp2  = (const float*)d_in[17];
    const float* Wq2  = (const float*)d_in[18];
    const float* bq2  = (const float*)d_in[19];
    const float* Wk2  = (const float*)d_in[20];
    const float* bk2  = (const float*)d_in[21];
    const float* Wo2  = (const float*)d_in[22];
    const float* bo2  = (const float*)d_in[23];
    const float* Wa2  = (const float*)d_in[24];
    const float* ba2  = (const float*)d_in[25];
    float* out = (float*)d_out;

    float *h, *h2, *q, *k, *v, *att, *S, *B1, *B2;
    cudaGetSymbolAddress((void**)&h,   g_h);
    cudaGetSymbolAddress((void**)&h2,  g_h2);
    cudaGetSymbolAddress((void**)&q,   g_q);
    cudaGetSymbolAddress((void**)&k,   g_k);
    cudaGetSymbolAddress((void**)&v,   g_v);
    cudaGetSymbolAddress((void**)&att, g_att);
    cudaGetSymbolAddress((void**)&S,   g_S);
    cudaGetSymbolAddress((void**)&B1,  g_B1);
    cudaGetSymbolAddress((void**)&B2,  g_B2);

    // Position log-bias for BOTH blocks: single pass over the 268 MB pe tensor
    posbias_kernel<<<dim3(RR, RR/128), 128>>>(pe, Wp1, bp1, Wp2, bp2, B1, B2);

    // fc1: h = x_flat @ Wfc1^T + bfc1      (1024 x 12544 x 1024)
    gemm_k<128,64,16,8,4,true,false><<<dim3(16,8,1),256>>>(
        x,nullptr,KFC1, Wfc1,KFC1, h,DD, RR,DD,KFC1, 1.f, bfc1,0, 0,0,0,0);

    // relation block 1
    relation_block(h, q, k, v, S, att, Wq1, bq1, Wk1, bk1, Wo1, bo1, B1);

    // h2 = relu([h | a1 | h+a1] @ Wa1^T + ba1)   (virtual concat, K=3072)
    gemm_k<128,64,16,8,4,true,true><<<dim3(16,8,1),256>>>(
        h,att,0, Wa1,3*DD, h2,DD, RR,DD,3*DD, 1.f, ba1,1, 0,0,0,0);

    // fc2: h = h2 @ Wfc2^T + bfc2
    gemm_k<64,64,16,4,4,true,false><<<dim3(16,16,1),256>>>(
        h2,nullptr,DD, Wfc2,DD, h,DD, RR,DD,DD, 1.f, bfc2,0, 0,0,0,0);

    // relation block 2
    relation_block(h, q, k, v, S, att, Wq2, bq2, Wk2, bk2, Wo2, bo2, B2);

    // out = relu([h | a2 | h+a2] @ Wa2^T + ba2)
    gemm_k<128,64,16,8,4,true,true><<<dim3(16,8,1),256>>>(
        h,att,0, Wa2,3*DD, out,DD, RR,DD,3*DD, 1.f, ba2,1, 0,0,0,0);
}